// round 3
// baseline (speedup 1.0000x reference)
#include <cuda_runtime.h>
#include <math.h>

#define BB 16
#define AA 3
#define CC 80
#define HH 76
#define WW 76
#define TT 50
#define HWW 5776                 /* 76*76 */
#define NCELL (BB*AA*HWW)        /* 277248 */
#define NPLANE (BB*AA)           /* 48 conf planes */
#define NF4 (NPLANE*(HWW/4))     /* 69312 float4s of conf data */
#define NB 64
#define NT 256
#define NWARPS ((NB*NT)/32)

// ---------------- device scratch ----------------
__device__ int g_nentries, g_nsup;
__device__ int g_ecell[BB*TT];
__device__ float g_etx[BB*TT], g_ety[BB*TT], g_etw[BB*TT], g_eth[BB*TT];
__device__ unsigned int g_ecls[BB*TT][3];
__device__ int g_sup[BB*TT*AA];
__device__ double g_acc[8];      // 0:x 1:y 2:w 3:h 4:confMasked 5:cls 6:confAll 7:supSum
__device__ unsigned int g_done;

// softplus clipped to 100 (== -clip(log(1-sigmoid(l)), -100))
__device__ __forceinline__ float sp(float l) {
    return fminf(log1pf(expf(l)), 100.0f);
}

// ---------------- kernel 1: build targets ----------------
__global__ void k_build(const float* __restrict__ tgt) {
    __shared__ float st[BB*TT*5];
    __shared__ unsigned int bits[BB*544];   // 17408 bits per batch >= A*H*W=17328
    for (int i = threadIdx.x; i < BB*TT*5; i += blockDim.x) st[i] = tgt[i];
    for (int i = threadIdx.x; i < BB*544;  i += blockDim.x) bits[i] = 0u;
    if (threadIdx.x < 8) g_acc[threadIdx.x] = 0.0;
    if (threadIdx.x == 0) { g_nentries = 0; g_nsup = 0; g_done = 0u; }
    __syncthreads();

    int b = threadIdx.x;
    if (b >= BB) return;

    const float aw[3] = {1.25f, 2.0f, 4.125f};     // ANCHORS / STRIDE (stride=8)
    const float ah[3] = {1.625f, 3.75f, 2.875f};

    int cells[TT];
    float ltx[TT], lty[TT], ltw[TT], lth[TT];
    unsigned int cm[TT][3];
    int cnt = 0;
    unsigned int* mybits = &bits[b*544];

    for (int t = 0; t < TT; t++) {
        const float* p = &st[(b*TT + t)*5];
        float cls = p[0], x = p[1], y = p[2], w = p[3], h = p[4];
        if ((cls + x + y + w + h) == 0.0f) continue;   // valid check
        float gx = x * WW, gy = y * HH, gw = w * WW, gh = h * HH;
        int gi = (int)gx, gj = (int)gy;
        bool inb = (gj >= 0) && (gj < HH) && (gi >= 0) && (gi < WW);
        float a1 = (gw + 1.0f) * (gh + 1.0f);
        float biou = -1.0f; int best = 0;
        #pragma unroll
        for (int a = 0; a < 3; a++) {
            float inter = fmaxf(fminf(gw, aw[a]) + 1.0f, 0.0f) *
                          fmaxf(fminf(gh, ah[a]) + 1.0f, 0.0f);
            float a2 = (aw[a] + 1.0f) * (ah[a] + 1.0f);
            float iou = inter / (a1 + a2 - inter + 1e-16f);
            if (iou > biou) { biou = iou; best = a; }
            if (iou > 0.5f && inb) {
                int lc = (a*HH + gj)*WW + gi;          // cell within batch
                unsigned int wd = lc >> 5, bt = 1u << (lc & 31);
                if (!(mybits[wd] & bt)) {              // dedup suppressed set
                    mybits[wd] |= bt;
                    int so = atomicAdd(&g_nsup, 1);
                    g_sup[so] = b*AA*HWW + lc;
                }
            }
        }
        if (inb) {
            int cell = ((b*AA + best)*HH + gj)*WW + gi;
            float tx = gx - (float)gi, ty = gy - (float)gj;
            float tw = logf(gw / aw[best] + 1e-16f);
            float th = logf(gh / ah[best] + 1e-16f);
            int ci = (int)cls;
            int j = -1;
            for (int k = 0; k < cnt; k++) if (cells[k] == cell) { j = k; break; }
            if (j < 0) { j = cnt++; cells[j] = cell; cm[j][0]=cm[j][1]=cm[j][2]=0u; }
            ltx[j] = tx; lty[j] = ty; ltw[j] = tw; lth[j] = th;  // last writer wins
            cm[j][ci >> 5] |= (1u << (ci & 31));                 // class bits OR
        }
    }
    int off = atomicAdd(&g_nentries, cnt);
    for (int k = 0; k < cnt; k++) {
        g_ecell[off+k] = cells[k];
        g_etx[off+k] = ltx[k]; g_ety[off+k] = lty[k];
        g_etw[off+k] = ltw[k]; g_eth[off+k] = lth[k];
        g_ecls[off+k][0] = cm[k][0]; g_ecls[off+k][1] = cm[k][1]; g_ecls[off+k][2] = cm[k][2];
    }
}

// ---------------- kernel 2: fused main ----------------
__global__ void __launch_bounds__(NT) k_main(const float* __restrict__ inp,
                                             float* __restrict__ out) {
    double acc[8];
    #pragma unroll
    for (int j = 0; j < 8; j++) acc[j] = 0.0;

    const int tid = blockIdx.x * NT + threadIdx.x;
    const int nthreads = NB * NT;

    // ---- phase 1: conf(bce, t=0) over ALL cells, float4 vectorized ----
    {
        const float4* inp4 = (const float4*)inp;
        for (int i = tid; i < NF4; i += nthreads) {
            int plane = i / (HWW/4);
            int q     = i - plane * (HWW/4);
            int b = plane / AA, a = plane - b * AA;
            // conf plane base in float4s: ((b*255 + a*85 + 4) * 5776) / 4
            int base4 = (b*255 + a*85 + 4) * (HWW/4);
            float4 v = inp4[base4 + q];
            acc[6] += (double)sp(v.x) + (double)sp(v.y) +
                      (double)sp(v.z) + (double)sp(v.w);
        }
    }

    // ---- phase 2: subtract suppressed cells' conf terms ----
    {
        int nsup = g_nsup;
        for (int s = tid; s < nsup; s += nthreads) {
            int cell = g_sup[s];
            int b = cell / (AA*HWW);
            int r = cell - b*(AA*HWW);
            int a = r / HWW;
            int hw = r - a*HWW;
            float l = inp[(size_t)(b*255 + a*85 + 4)*HWW + hw];
            acc[7] += (double)sp(l);
        }
    }

    // ---- phase 3: masked-cell losses, one warp per entry ----
    {
        int lane = threadIdx.x & 31;
        int wid  = tid >> 5;
        int nE = g_nentries;
        for (int e = wid; e < nE; e += NWARPS) {
            int cell = g_ecell[e];
            int b = cell / (AA*HWW);
            int r = cell - b*(AA*HWW);
            int a = r / HWW;
            int hw = r - a*HWW;
            const float* base = inp + (size_t)(b*255 + a*85)*HWW + hw;
            unsigned int m0 = g_ecls[e][0], m1 = g_ecls[e][1], m2 = g_ecls[e][2];
            #pragma unroll
            for (int k = 0; k < 3; k++) {
                int ch = lane + 32*k;
                if (ch < 85) {
                    float l = base[(size_t)ch * HWW];
                    if (ch >= 5) {
                        int c = ch - 5;
                        unsigned int mm = (k == 0) ? ((c < 27) ? m0 : m0)   // k=0: c=lane-5<27
                                        : (k == 1) ? ((c < 32) ? m0 : m1)   // k=1: c=27..58
                                                   : ((c < 64) ? m1 : m2);  // k=2: c=59..79
                        float t = ((mm >> (c & 31)) & 1u) ? 1.0f : 0.0f;
                        acc[5] += (double)(sp(l) - t * l);
                    } else if (ch == 0) {
                        acc[0] += (double)(sp(l) - g_etx[e] * l);
                    } else if (ch == 1) {
                        acc[1] += (double)(sp(l) - g_ety[e] * l);
                    } else if (ch == 2) {
                        float d = l - g_etw[e]; acc[2] += (double)(d * d);
                    } else if (ch == 3) {
                        float d = l - g_eth[e]; acc[3] += (double)(d * d);
                    } else { // ch == 4: bce(conf, 1)
                        acc[4] += (double)fminf(log1pf(expf(-l)), 100.0f);
                    }
                }
            }
        }
    }

    // ---- block reduction: warp shuffles -> shared atomics -> 1 global/addr ----
    __shared__ double sacc[8];
    if (threadIdx.x < 8) sacc[threadIdx.x] = 0.0;
    __syncthreads();
    #pragma unroll
    for (int j = 0; j < 8; j++) {
        double v = acc[j];
        #pragma unroll
        for (int o = 16; o > 0; o >>= 1) v += __shfl_down_sync(0xffffffffu, v, o);
        if ((threadIdx.x & 31) == 0) atomicAdd(&sacc[j], v);
    }
    __syncthreads();
    if (threadIdx.x < 8) atomicAdd(&g_acc[threadIdx.x], sacc[threadIdx.x]);

    // ---- last-block final combine ----
    __threadfence();
    __shared__ unsigned int ticket;
    if (threadIdx.x == 0) ticket = atomicAdd(&g_done, 1u);
    __syncthreads();
    if (ticket == NB - 1 && threadIdx.x == 0) {
        double A0 = atomicAdd(&g_acc[0], 0.0), A1 = atomicAdd(&g_acc[1], 0.0);
        double A2 = atomicAdd(&g_acc[2], 0.0), A3 = atomicAdd(&g_acc[3], 0.0);
        double A4 = atomicAdd(&g_acc[4], 0.0), A5 = atomicAdd(&g_acc[5], 0.0);
        double A6 = atomicAdd(&g_acc[6], 0.0), A7 = atomicAdd(&g_acc[7], 0.0);
        double Nd   = (double)NCELL;
        double n_m  = (double)g_nentries;
        double n_nm = (double)(NCELL - g_nsup);
        double lx = (A0 / Nd) / n_m;
        double ly = (A1 / Nd) / n_m;
        double lw = (A2 / Nd) / n_m;
        double lh = (A3 / Nd) / n_m;
        double lconf = (A4 / Nd) / n_m + 0.5 * ((A6 - A7) / Nd) / n_nm;
        double lcls  = A5 / (n_m * (double)CC) / n_m;
        double loss  = 2.5 * (lx + ly) + 2.5 * (lw + lh) + lconf + lcls;
        out[0] = (float)loss;
        out[1] = (float)lx;    out[2] = (float)ly;
        out[3] = (float)lw;    out[4] = (float)lh;
        out[5] = (float)lconf; out[6] = (float)lcls;
    }
}

// ---------------- launch ----------------
extern "C" void kernel_launch(void* const* d_in, const int* in_sizes, int n_in,
                              void* d_out, int out_size) {
    const float* inp;
    const float* tgt;
    if (in_sizes[0] > in_sizes[1]) { inp = (const float*)d_in[0]; tgt = (const float*)d_in[1]; }
    else                           { inp = (const float*)d_in[1]; tgt = (const float*)d_in[0]; }
    float* out = (float*)d_out;

    k_build<<<1, 128>>>(tgt);
    k_main <<<NB, NT>>>(inp, out);
}

// round 9
// speedup vs baseline: 5.2388x; 5.2388x over previous
#include <cuda_runtime.h>
#include <math.h>

#define BB 16
#define AA 3
#define CC 80
#define HH 76
#define WW 76
#define TT 50
#define HWW 5776                 /* 76*76 */
#define NCELL (BB*AA*HWW)        /* 277248 */
#define NF4 (BB*AA*(HWW/4))      /* 69312 float4s of conf data */
#define NTGT (BB*TT)             /* 800 */
#define NB 296
#define NT 256
#define NWARPS ((NB*NT)/32)

// ---------------- device scratch ----------------
__device__ int g_nentries, g_nsup;
__device__ int g_ecell[NTGT];
__device__ float g_etx[NTGT], g_ety[NTGT], g_etw[NTGT], g_eth[NTGT];
__device__ unsigned int g_ecls[NTGT][3];
__device__ int g_sup[NTGT*AA];
__device__ double g_acc[8];      // 0:x 1:y 2:w 3:h 4:confMasked 5:cls 6:confAll 7:supSum
__device__ unsigned int g_done;

// stable fast softplus, clipped at 100: == -clip(log(1-sigmoid(l)), -100)
__device__ __forceinline__ float sp(float l) {
    float v = fmaxf(l, 0.0f) + __logf(1.0f + __expf(-fabsf(l)));
    return fminf(v, 100.0f);
}

// ---------------- kernel 1: parallel target build ----------------
__global__ void __launch_bounds__(832) k_build(const float* __restrict__ tgt) {
    __shared__ int s_cell[NTGT];
    __shared__ int s_cls[NTGT];
    __shared__ unsigned int bits[BB*544];   // suppressed-cell bitmap per batch
    const int tid = threadIdx.x;

    for (int i = tid; i < BB*544; i += blockDim.x) bits[i] = 0u;
    if (tid < 8) g_acc[tid] = 0.0;
    if (tid == 0) { g_nentries = 0; g_nsup = 0; g_done = 0u; }
    __syncthreads();

    const float aw[3] = {1.25f, 2.0f, 4.125f};     // ANCHORS / STRIDE (stride=8)
    const float ah[3] = {1.625f, 3.75f, 2.875f};

    int cell = -1;
    float tx = 0.f, ty = 0.f, tw = 0.f, th = 0.f;
    int b = tid / TT, t = tid - b * TT;

    if (tid < NTGT) {
        const float* p = tgt + (size_t)tid * 5;
        float cls = p[0], x = p[1], y = p[2], w = p[3], h = p[4];
        bool valid = (cls + x + y + w + h) != 0.0f;
        float gx = x * WW, gy = y * HH, gw = w * WW, gh = h * HH;
        int gi = (int)gx, gj = (int)gy;
        bool inb = (gj >= 0) && (gj < HH) && (gi >= 0) && (gi < WW);
        float a1 = (gw + 1.0f) * (gh + 1.0f);
        float biou = -1.0f; int best = 0;
        #pragma unroll
        for (int a = 0; a < 3; a++) {
            float inter = fmaxf(fminf(gw, aw[a]) + 1.0f, 0.0f) *
                          fmaxf(fminf(gh, ah[a]) + 1.0f, 0.0f);
            float a2 = (aw[a] + 1.0f) * (ah[a] + 1.0f);
            float iou = inter / (a1 + a2 - inter + 1e-16f);
            if (iou > biou) { biou = iou; best = a; }
            if (valid && inb && iou > 0.5f) {
                int lc = (a*HH + gj)*WW + gi;
                unsigned int bt = 1u << (lc & 31);
                unsigned int old = atomicOr(&bits[b*544 + (lc >> 5)], bt);
                if (!(old & bt)) {                    // first to suppress this cell
                    int so = atomicAdd(&g_nsup, 1);
                    g_sup[so] = b*AA*HWW + lc;
                }
            }
        }
        if (valid && inb) {
            cell = ((b*AA + best)*HH + gj)*WW + gi;
            tx = gx - (float)gi; ty = gy - (float)gj;
            tw = __logf(gw / aw[best] + 1e-16f);
            th = __logf(gh / ah[best] + 1e-16f);
        }
        s_cell[tid] = cell;
        s_cls[tid]  = (int)cls;
    }
    __syncthreads();

    if (tid < NTGT && cell >= 0) {
        // last-writer-wins: am I the latest target in my batch mapping to this cell?
        bool winner = true;
        for (int t2 = t + 1; t2 < TT; t2++)
            if (s_cell[b*TT + t2] == cell) { winner = false; break; }
        if (winner) {
            unsigned int m0 = 0u, m1 = 0u, m2 = 0u;
            for (int t2 = 0; t2 <= t; t2++) {          // class bits OR over ALL writers
                if (s_cell[b*TT + t2] == cell) {
                    int ci = s_cls[b*TT + t2];
                    if (ci < 32)      m0 |= 1u << ci;
                    else if (ci < 64) m1 |= 1u << (ci - 32);
                    else              m2 |= 1u << (ci - 64);
                }
            }
            int off = atomicAdd(&g_nentries, 1);
            g_ecell[off] = cell;
            g_etx[off] = tx; g_ety[off] = ty;
            g_etw[off] = tw; g_eth[off] = th;
            g_ecls[off][0] = m0; g_ecls[off][1] = m1; g_ecls[off][2] = m2;
        }
    }
}

// ---------------- kernel 2: fused main (float partials, fp64 only at block exit) --
__global__ void __launch_bounds__(NT) k_main(const float* __restrict__ inp,
                                             float* __restrict__ out) {
    float acc[8];
    #pragma unroll
    for (int j = 0; j < 8; j++) acc[j] = 0.0f;

    const int tid = blockIdx.x * NT + threadIdx.x;
    const int nthreads = NB * NT;

    // ---- phase 1: bce(conf, 0) over ALL cells, float4 vectorized ----
    {
        const float4* inp4 = (const float4*)inp;
        for (int i = tid; i < NF4; i += nthreads) {
            int plane = i / (HWW/4);
            int q     = i - plane * (HWW/4);
            int b = plane / AA, a = plane - b * AA;
            int base4 = (b*255 + a*85 + 4) * (HWW/4);
            float4 v = inp4[base4 + q];
            acc[6] += sp(v.x) + sp(v.y) + sp(v.z) + sp(v.w);
        }
    }

    // ---- phase 2: subtract suppressed cells' conf terms ----
    {
        int nsup = g_nsup;
        for (int s = tid; s < nsup; s += nthreads) {
            int cell = g_sup[s];
            int b = cell / (AA*HWW);
            int r = cell - b*(AA*HWW);
            int a = r / HWW;
            int hw = r - a*HWW;
            acc[7] += sp(inp[(size_t)(b*255 + a*85 + 4)*HWW + hw]);
        }
    }

    // ---- phase 3: masked-cell losses, one warp per entry ----
    {
        int lane = threadIdx.x & 31;
        int wid  = tid >> 5;
        int nE = g_nentries;
        for (int e = wid; e < nE; e += NWARPS) {
            int cell = g_ecell[e];
            int b = cell / (AA*HWW);
            int r = cell - b*(AA*HWW);
            int a = r / HWW;
            int hw = r - a*HWW;
            const float* base = inp + (size_t)(b*255 + a*85)*HWW + hw;
            unsigned int m0 = g_ecls[e][0], m1 = g_ecls[e][1], m2 = g_ecls[e][2];
            #pragma unroll
            for (int k = 0; k < 3; k++) {
                int ch = lane + 32*k;
                if (ch < 85) {
                    float l = base[(size_t)ch * HWW];
                    if (ch >= 5) {
                        int c = ch - 5;
                        unsigned int mm = (c < 32) ? m0 : ((c < 64) ? m1 : m2);
                        float tt = ((mm >> (c & 31)) & 1u) ? 1.0f : 0.0f;
                        acc[5] += sp(l) - tt * l;
                    } else if (ch == 0) {
                        acc[0] += sp(l) - g_etx[e] * l;
                    } else if (ch == 1) {
                        acc[1] += sp(l) - g_ety[e] * l;
                    } else if (ch == 2) {
                        float d = l - g_etw[e]; acc[2] += d * d;
                    } else if (ch == 3) {
                        float d = l - g_eth[e]; acc[3] += d * d;
                    } else { // ch == 4: bce(conf, 1) = sp(-l)
                        acc[4] += sp(-l);
                    }
                }
            }
        }
    }

    // ---- block reduction: warp shuffle (f32) -> shared atomics -> fp64 global ----
    __shared__ float sacc[8];
    if (threadIdx.x < 8) sacc[threadIdx.x] = 0.0f;
    __syncthreads();
    #pragma unroll
    for (int j = 0; j < 8; j++) {
        float v = acc[j];
        #pragma unroll
        for (int o = 16; o > 0; o >>= 1) v += __shfl_down_sync(0xffffffffu, v, o);
        if ((threadIdx.x & 31) == 0 && v != 0.0f) atomicAdd(&sacc[j], v);
    }
    __syncthreads();
    if (threadIdx.x < 8) atomicAdd(&g_acc[threadIdx.x], (double)sacc[threadIdx.x]);

    // ---- last-block final combine ----
    __threadfence();
    __shared__ unsigned int ticket;
    if (threadIdx.x == 0) ticket = atomicAdd(&g_done, 1u);
    __syncthreads();
    if (ticket == NB - 1 && threadIdx.x == 0) {
        // All other blocks' atomics are ordered before their g_done increment by
        // the fence; we are the last incrementer, so plain volatile reads suffice.
        volatile double* ga = g_acc;
        double A0 = ga[0], A1 = ga[1], A2 = ga[2], A3 = ga[3];
        double A4 = ga[4], A5 = ga[5], A6 = ga[6], A7 = ga[7];
        double Nd   = (double)NCELL;
        double n_m  = (double)g_nentries;
        double n_nm = (double)(NCELL - g_nsup);
        double lx = (A0 / Nd) / n_m;
        double ly = (A1 / Nd) / n_m;
        double lw = (A2 / Nd) / n_m;
        double lh = (A3 / Nd) / n_m;
        double lconf = (A4 / Nd) / n_m + 0.5 * ((A6 - A7) / Nd) / n_nm;
        double lcls  = A5 / (n_m * (double)CC) / n_m;
        double loss  = 2.5 * (lx + ly) + 2.5 * (lw + lh) + lconf + lcls;
        out[0] = (float)loss;
        out[1] = (float)lx;    out[2] = (float)ly;
        out[3] = (float)lw;    out[4] = (float)lh;
        out[5] = (float)lconf; out[6] = (float)lcls;
    }
}

// ---------------- launch ----------------
extern "C" void kernel_launch(void* const* d_in, const int* in_sizes, int n_in,
                              void* d_out, int out_size) {
    const float* inp;
    const float* tgt;
    if (in_sizes[0] > in_sizes[1]) { inp = (const float*)d_in[0]; tgt = (const float*)d_in[1]; }
    else                           { inp = (const float*)d_in[1]; tgt = (const float*)d_in[0]; }
    float* out = (float*)d_out;

    k_build<<<1, 832>>>(tgt);
    k_main <<<NB, NT>>>(inp, out);
}